// round 6
// baseline (speedup 1.0000x reference)
#include <cuda_runtime.h>
#include <cuda_bf16.h>
#include <stdint.h>

#define N_NODES 50000
#define N_EDGES 800000
#define C_IN    256
#define C_HID   128
#define C_OUT   64

// ---------------- scratch (static device globals; no allocation) ----------------
__device__ int   g_is64;
__device__ int   g_cnt[N_NODES];
__device__ float g_dinv[N_NODES];
__device__ int   g_rowptr[N_NODES + 1];
__device__ int   g_fill[N_NODES];
__device__ int   g_srcidx[N_EDGES];
__device__ float g_norm[N_EDGES];
__device__ float g_h1[(size_t)N_NODES * C_HID];   // X @ W1
__device__ float g_a1[(size_t)N_NODES * C_HID];   // relu(aggregate(h1) + b1)
__device__ float g_h2[(size_t)N_NODES * C_OUT];   // a1 @ W2

// ---------------- edge dtype detection ----------------
__global__ void detect_dtype_kernel(const void* ei) {
    const long long* e64 = (const long long*)ei;
    bool ok = true;
    for (int i = 0; i < 8; i++) {
        long long s = e64[i];
        long long d = e64[N_EDGES + i];
        if (s < 0 || s >= N_NODES || d < 0 || d >= N_NODES) ok = false;
    }
    g_is64 = ok ? 1 : 0;
}

__device__ __forceinline__ int edge_at(const void* ei, size_t idx, int is64) {
    long long v;
    if (is64) v = ((const long long*)ei)[idx];
    else      v = (long long)((const int*)ei)[idx];
    v = v < 0 ? 0 : (v >= N_NODES ? N_NODES - 1 : v);
    return (int)v;
}

// ---------------- CSR build ----------------
__global__ void zero_cnt_kernel() {
    int i = blockIdx.x * blockDim.x + threadIdx.x;
    if (i < N_NODES) g_cnt[i] = 0;
}

__global__ void count_kernel(const void* __restrict__ ei) {
    int e = blockIdx.x * blockDim.x + threadIdx.x;
    if (e < N_EDGES) {
        int d = edge_at(ei, (size_t)N_EDGES + e, g_is64);
        atomicAdd(&g_cnt[d], 1);
    }
}

__global__ void dinv_kernel() {
    int i = blockIdx.x * blockDim.x + threadIdx.x;
    if (i < N_NODES) {
        float deg = (float)g_cnt[i] + 1.0f;
        g_dinv[i] = rsqrtf(deg);
    }
}

__global__ void scan_kernel() {
    __shared__ int sums[1024];
    const int tid = threadIdx.x;
    const int CHUNK = (N_NODES + 1023) / 1024;
    int begin = tid * CHUNK;
    int end   = min(begin + CHUNK, N_NODES);
    int s = 0;
    for (int i = begin; i < end; i++) s += g_cnt[i];
    sums[tid] = s;
    __syncthreads();
    for (int off = 1; off < 1024; off <<= 1) {
        int v = 0;
        if (tid >= off) v = sums[tid - off];
        __syncthreads();
        if (tid >= off) sums[tid] += v;
        __syncthreads();
    }
    int run = (tid == 0) ? 0 : sums[tid - 1];
    for (int i = begin; i < end; i++) {
        g_rowptr[i] = run;
        g_fill[i]   = run;
        run += g_cnt[i];
    }
    if (tid == 0) g_rowptr[N_NODES] = N_EDGES;
}

__global__ void scatter_kernel(const void* __restrict__ ei) {
    int e = blockIdx.x * blockDim.x + threadIdx.x;
    if (e < N_EDGES) {
        int is64 = g_is64;
        int s = edge_at(ei, e, is64);
        int d = edge_at(ei, (size_t)N_EDGES + e, is64);
        int p = atomicAdd(&g_fill[d], 1);
        g_srcidx[p] = s;
        g_norm[p]   = g_dinv[s] * g_dinv[d];
    }
}

// ---------------- 3xTF32 tensor-core GEMM ----------------
__device__ __forceinline__ uint32_t f2tf32(float x) {
    uint32_t r;
    asm("cvt.rna.tf32.f32 %0, %1;" : "=r"(r) : "f"(x));
    return r;
}

#define MMA_TF32(c, a, b)                                                     \
    asm volatile(                                                             \
        "mma.sync.aligned.m16n8k8.row.col.f32.tf32.tf32.f32 "                 \
        "{%0,%1,%2,%3},{%4,%5,%6,%7},{%8,%9},{%0,%1,%2,%3};"                  \
        : "+f"((c)[0]), "+f"((c)[1]), "+f"((c)[2]), "+f"((c)[3])              \
        : "r"((a)[0]), "r"((a)[1]), "r"((a)[2]), "r"((a)[3]),                 \
          "r"((b)[0]), "r"((b)[1]))

// C[M,NN] = A[M,KK] @ B[KK,NN].  LAYER 0: A=x, C=g_h1.  LAYER 1: A=g_a1, C=g_h2.
template <int BM, int BN, int BK, int WARPS_M, int WARPS_N, int NN, int KK, int LAYER>
__global__ void __launch_bounds__(256)
mma_gemm_kernel(const float* __restrict__ A_ext, const float* __restrict__ B, int M) {
    const float* __restrict__ A = (LAYER == 0) ? A_ext : (const float*)g_a1;
    float* __restrict__ C = (LAYER == 0) ? (float*)g_h1 : (float*)g_h2;

    constexpr int BKP = BK + 1;
    constexpr int WM = BM / WARPS_M;
    constexpr int WN = BN / WARPS_N;
    constexpr int MI = WM / 16;
    constexpr int NI = WN / 8;
    constexpr int A4 = BM * BK / 4;
    constexpr int B4 = BK * BN / 4;

    __shared__ float Ah[BM * BKP], Al[BM * BKP];
    __shared__ float Bh[BN * BKP], Bl[BN * BKP];

    const int tid  = threadIdx.x;
    const int wid  = tid >> 5;
    const int lane = tid & 31;
    const int g    = lane >> 2;   // group (row within frag)
    const int t    = lane & 3;    // thread in group (col within frag)
    const int wm   = (wid / WARPS_N) * WM;
    const int wn   = (wid % WARPS_N) * WN;
    const int block_m = blockIdx.x * BM;

    float acc[MI][NI][4];
#pragma unroll
    for (int mi = 0; mi < MI; mi++)
#pragma unroll
        for (int ni = 0; ni < NI; ni++)
#pragma unroll
            for (int j = 0; j < 4; j++) acc[mi][ni][j] = 0.0f;

    for (int k0 = 0; k0 < KK; k0 += BK) {
        // ---- fill A tile (hi/lo tf32 split) ----
#pragma unroll
        for (int i = tid; i < A4; i += 256) {
            int row = i / (BK / 4);
            int c4  = i % (BK / 4);
            int gm  = block_m + row;
            float4 v = make_float4(0.f, 0.f, 0.f, 0.f);
            if (gm < M) v = *(const float4*)&A[(size_t)gm * KK + k0 + c4 * 4];
            float f[4] = {v.x, v.y, v.z, v.w};
#pragma unroll
            for (int j = 0; j < 4; j++) {
                uint32_t hb = f2tf32(f[j]);
                float hf = __uint_as_float(hb);
                uint32_t lb = f2tf32(f[j] - hf);
                Ah[row * BKP + c4 * 4 + j] = hf;
                Al[row * BKP + c4 * 4 + j] = __uint_as_float(lb);
            }
        }
        // ---- fill B tile transposed (Bs[n][k]) with hi/lo split ----
#pragma unroll
        for (int i = tid; i < B4; i += 256) {
            int kr = i / (BN / 4);
            int n4 = i % (BN / 4);
            float4 v = *(const float4*)&B[(size_t)(k0 + kr) * NN + n4 * 4];
            float f[4] = {v.x, v.y, v.z, v.w};
#pragma unroll
            for (int j = 0; j < 4; j++) {
                int n = n4 * 4 + j;
                uint32_t hb = f2tf32(f[j]);
                float hf = __uint_as_float(hb);
                uint32_t lb = f2tf32(f[j] - hf);
                Bh[n * BKP + kr] = hf;
                Bl[n * BKP + kr] = __uint_as_float(lb);
            }
        }
        __syncthreads();

#pragma unroll
        for (int kk = 0; kk < BK / 8; kk++) {
            const int c = kk * 8 + t;
            uint32_t ah[MI][4], al[MI][4];
#pragma unroll
            for (int mi = 0; mi < MI; mi++) {
                int r = wm + mi * 16;
                ah[mi][0] = __float_as_uint(Ah[(r + g) * BKP + c]);
                ah[mi][1] = __float_as_uint(Ah[(r + g + 8) * BKP + c]);
                ah[mi][2] = __float_as_uint(Ah[(r + g) * BKP + c + 4]);
                ah[mi][3] = __float_as_uint(Ah[(r + g + 8) * BKP + c + 4]);
                al[mi][0] = __float_as_uint(Al[(r + g) * BKP + c]);
                al[mi][1] = __float_as_uint(Al[(r + g + 8) * BKP + c]);
                al[mi][2] = __float_as_uint(Al[(r + g) * BKP + c + 4]);
                al[mi][3] = __float_as_uint(Al[(r + g + 8) * BKP + c + 4]);
            }
            uint32_t bh[NI][2], bl[NI][2];
#pragma unroll
            for (int ni = 0; ni < NI; ni++) {
                int n = wn + ni * 8 + g;
                bh[ni][0] = __float_as_uint(Bh[n * BKP + kk * 8 + t]);
                bh[ni][1] = __float_as_uint(Bh[n * BKP + kk * 8 + t + 4]);
                bl[ni][0] = __float_as_uint(Bl[n * BKP + kk * 8 + t]);
                bl[ni][1] = __float_as_uint(Bl[n * BKP + kk * 8 + t + 4]);
            }
#pragma unroll
            for (int mi = 0; mi < MI; mi++)
#pragma unroll
                for (int ni = 0; ni < NI; ni++) {
                    MMA_TF32(acc[mi][ni], ah[mi], bh[ni]);
                    MMA_TF32(acc[mi][ni], ah[mi], bl[ni]);
                    MMA_TF32(acc[mi][ni], al[mi], bh[ni]);
                }
        }
        __syncthreads();
    }

    // ---- epilogue ----
#pragma unroll
    for (int mi = 0; mi < MI; mi++) {
#pragma unroll
        for (int ni = 0; ni < NI; ni++) {
            int r0 = block_m + wm + mi * 16 + g;
            int c0 = wn + ni * 8 + 2 * t;
            if (r0 < M)
                *(float2*)&C[(size_t)r0 * NN + c0] =
                    make_float2(acc[mi][ni][0], acc[mi][ni][1]);
            if (r0 + 8 < M)
                *(float2*)&C[(size_t)(r0 + 8) * NN + c0] =
                    make_float2(acc[mi][ni][2], acc[mi][ni][3]);
        }
    }
}

// ---------------- aggregation (one warp per dst node) ----------------
__global__ void agg128_relu_kernel(const float* __restrict__ bias) {
    const float* __restrict__ h = (const float*)g_h1;
    float* __restrict__ out = (float*)g_a1;
    const int warp = blockIdx.x * (blockDim.x >> 5) + (threadIdx.x >> 5);
    const int lane = threadIdx.x & 31;
    if (warp >= N_NODES) return;

    const int start = g_rowptr[warp];
    const int end   = g_rowptr[warp + 1];

    float4 acc = make_float4(0.f, 0.f, 0.f, 0.f);
    for (int base = start; base < end; base += 32) {
        int e = base + lane;
        int s = 0; float nm = 0.f;
        if (e < end) { s = g_srcidx[e]; nm = g_norm[e]; }
        int cnt = min(32, end - base);
        for (int j = 0; j < cnt; j++) {
            int   ss = __shfl_sync(0xffffffffu, s, j);
            float nn = __shfl_sync(0xffffffffu, nm, j);
            float4 v = *(const float4*)&h[(size_t)ss * C_HID + lane * 4];
            acc.x += v.x * nn; acc.y += v.y * nn;
            acc.z += v.z * nn; acc.w += v.w * nn;
        }
    }
    float dv = g_dinv[warp];
    float sn = dv * dv;
    float4 v = *(const float4*)&h[(size_t)warp * C_HID + lane * 4];
    acc.x += v.x * sn; acc.y += v.y * sn; acc.z += v.z * sn; acc.w += v.w * sn;
    float4 b = *(const float4*)&bias[lane * 4];
    acc.x += b.x; acc.y += b.y; acc.z += b.z; acc.w += b.w;
    acc.x = fmaxf(acc.x, 0.f); acc.y = fmaxf(acc.y, 0.f);
    acc.z = fmaxf(acc.z, 0.f); acc.w = fmaxf(acc.w, 0.f);
    *(float4*)&out[(size_t)warp * C_HID + lane * 4] = acc;
}

__global__ void agg64_kernel(const float* __restrict__ bias,
                             float* __restrict__ out) {
    const float* __restrict__ h = (const float*)g_h2;
    const int warp = blockIdx.x * (blockDim.x >> 5) + (threadIdx.x >> 5);
    const int lane = threadIdx.x & 31;
    if (warp >= N_NODES) return;

    const int start = g_rowptr[warp];
    const int end   = g_rowptr[warp + 1];

    float2 acc = make_float2(0.f, 0.f);
    for (int base = start; base < end; base += 32) {
        int e = base + lane;
        int s = 0; float nm = 0.f;
        if (e < end) { s = g_srcidx[e]; nm = g_norm[e]; }
        int cnt = min(32, end - base);
        for (int j = 0; j < cnt; j++) {
            int   ss = __shfl_sync(0xffffffffu, s, j);
            float nn = __shfl_sync(0xffffffffu, nm, j);
            float2 v = *(const float2*)&h[(size_t)ss * C_OUT + lane * 2];
            acc.x += v.x * nn; acc.y += v.y * nn;
        }
    }
    float dv = g_dinv[warp];
    float sn = dv * dv;
    float2 v = *(const float2*)&h[(size_t)warp * C_OUT + lane * 2];
    acc.x += v.x * sn; acc.y += v.y * sn;
    float2 b = *(const float2*)&bias[lane * 2];
    acc.x += b.x; acc.y += b.y;
    *(float2*)&out[(size_t)warp * C_OUT + lane * 2] = acc;
}

// ---------------- launch ----------------
extern "C" void kernel_launch(void* const* d_in, const int* in_sizes, int n_in,
                              void* d_out, int out_size) {
    const float* x  = (const float*)d_in[0];
    const void*  ei = d_in[1];
    const float* W1 = (const float*)d_in[2];
    const float* b1 = (const float*)d_in[3];
    const float* W2 = (const float*)d_in[4];
    const float* b2 = (const float*)d_in[5];
    float* out = (float*)d_out;

    const int TB = 256;
    const int nodeBlocks = (N_NODES + TB - 1) / TB;
    const int edgeBlocks = (N_EDGES + TB - 1) / TB;

    detect_dtype_kernel<<<1, 1>>>(ei);
    // layer 1 GEMM is independent of the CSR build: launch it early so it
    // overlaps nothing but occupies the profiler window.
    {
        constexpr int BM = 64;
        int grid = (N_NODES + BM - 1) / BM;
        mma_gemm_kernel<BM, 128, 16, 2, 4, C_HID, C_IN, 0><<<grid, 256>>>(x, W1, N_NODES);
    }
    zero_cnt_kernel<<<nodeBlocks, TB>>>();
    count_kernel<<<edgeBlocks, TB>>>(ei);
    dinv_kernel<<<nodeBlocks, TB>>>();
    scan_kernel<<<1, 1024>>>();
    scatter_kernel<<<edgeBlocks, TB>>>(ei);

    // g_a1 = relu(aggregate(g_h1) + b1)
    {
        const int WPB = 8;
        int grid = (N_NODES + WPB - 1) / WPB;
        agg128_relu_kernel<<<grid, WPB * 32>>>(b1);
    }
    // layer 2: g_h2 = g_a1 @ W2
    {
        constexpr int BM = 64;
        int grid = (N_NODES + BM - 1) / BM;
        mma_gemm_kernel<BM, 64, 16, 4, 2, C_OUT, C_HID, 1><<<grid, 256>>>(nullptr, W2, N_NODES);
    }
    // out = aggregate(g_h2) + b2
    {
        const int WPB = 8;
        int grid = (N_NODES + WPB - 1) / WPB;
        agg64_kernel<<<grid, WPB * 32>>>(b2, out);
    }
}

// round 9
// speedup vs baseline: 1.2973x; 1.2973x over previous
#include <cuda_runtime.h>
#include <cuda_bf16.h>
#include <stdint.h>

#define N_NODES 50000
#define N_EDGES 800000
#define C_IN    256
#define C_HID   128
#define C_OUT   64

// ---------------- scratch (static device globals; no allocation) ----------------
// RULE (learned R1/R7): never pass these as kernel arguments from host code —
// reference them directly inside device code only.
__device__ int   g_is64;
__device__ int   g_cnt[N_NODES];
__device__ float g_dinv[N_NODES];
__device__ int   g_rowptr[N_NODES + 1];
__device__ int   g_fill[N_NODES];
__device__ int   g_srcidx[N_EDGES];
__device__ float g_norm[N_EDGES];
__device__ float g_h1[(size_t)N_NODES * C_HID];       // X @ W1 (fp32)
__device__ float g_h2[(size_t)N_NODES * C_OUT];       // a1 @ W2 (fp32)
// a1 stored as bf16 hi/lo pairs (2 features per uint32), k-major per row
__device__ uint32_t g_a1h[(size_t)N_NODES * (C_HID / 2)];
__device__ uint32_t g_a1l[(size_t)N_NODES * (C_HID / 2)];
// weights pre-split+transposed: W^T [n][k] as bf16 pairs
__device__ uint32_t g_w1h[C_HID * (C_IN / 2)];
__device__ uint32_t g_w1l[C_HID * (C_IN / 2)];
__device__ uint32_t g_w2h[C_OUT * (C_HID / 2)];
__device__ uint32_t g_w2l[C_OUT * (C_HID / 2)];

// ---------------- helpers ----------------
__device__ __forceinline__ uint32_t packbf2(float x, float y) {
    __nv_bfloat162 v = __floats2bfloat162_rn(x, y);   // x -> low half
    return *(uint32_t*)&v;
}
__device__ __forceinline__ void split2(float x, float y, uint32_t& hi, uint32_t& lo) {
    __nv_bfloat16 hx = __float2bfloat16_rn(x);
    __nv_bfloat16 hy = __float2bfloat16_rn(y);
    __nv_bfloat162 h = __halves2bfloat162(hx, hy);
    hi = *(uint32_t*)&h;
    lo = packbf2(x - __bfloat162float(hx), y - __bfloat162float(hy));
}

#define MMA_BF16(c, a, b)                                                     \
    asm volatile(                                                             \
        "mma.sync.aligned.m16n8k16.row.col.f32.bf16.bf16.f32 "                \
        "{%0,%1,%2,%3},{%4,%5,%6,%7},{%8,%9},{%0,%1,%2,%3};"                  \
        : "+f"((c)[0]), "+f"((c)[1]), "+f"((c)[2]), "+f"((c)[3])              \
        : "r"((a)[0]), "r"((a)[1]), "r"((a)[2]), "r"((a)[3]),                 \
          "r"((b)[0]), "r"((b)[1]))

// ---------------- edge dtype detection ----------------
__global__ void detect_dtype_kernel(const void* ei) {
    const long long* e64 = (const long long*)ei;
    bool ok = true;
    for (int i = 0; i < 8; i++) {
        long long s = e64[i];
        long long d = e64[N_EDGES + i];
        if (s < 0 || s >= N_NODES || d < 0 || d >= N_NODES) ok = false;
    }
    g_is64 = ok ? 1 : 0;
}

__device__ __forceinline__ int edge_at(const void* ei, size_t idx, int is64) {
    long long v;
    if (is64) v = ((const long long*)ei)[idx];
    else      v = (long long)((const int*)ei)[idx];
    v = v < 0 ? 0 : (v >= N_NODES ? N_NODES - 1 : v);
    return (int)v;
}

// ---------------- weight prep (split + transpose; globals referenced in device code) ----------------
// W [K][N] row-major -> Wt hi/lo pair arrays [N][K/2]
template <int LAYER>
__global__ void wprep_kernel(const float* __restrict__ W) {
    constexpr int K = (LAYER == 0) ? C_IN  : C_HID;
    constexpr int N = (LAYER == 0) ? C_HID : C_OUT;
    uint32_t* __restrict__ Wh = (LAYER == 0) ? g_w1h : g_w2h;
    uint32_t* __restrict__ Wl = (LAYER == 0) ? g_w1l : g_w2l;
    int idx = blockIdx.x * blockDim.x + threadIdx.x;   // over N * K/2
    if (idx >= N * (K / 2)) return;
    int n  = idx / (K / 2);
    int kp = idx % (K / 2);
    float f0 = W[(size_t)(2 * kp) * N + n];
    float f1 = W[(size_t)(2 * kp + 1) * N + n];
    uint32_t hi, lo;
    split2(f0, f1, hi, lo);
    Wh[idx] = hi;
    Wl[idx] = lo;
}

// ---------------- CSR build ----------------
__global__ void zero_cnt_kernel() {
    int i = blockIdx.x * blockDim.x + threadIdx.x;
    if (i < N_NODES) g_cnt[i] = 0;
}

__global__ void count_kernel(const void* __restrict__ ei) {
    int e = blockIdx.x * blockDim.x + threadIdx.x;
    if (e < N_EDGES) {
        int d = edge_at(ei, (size_t)N_EDGES + e, g_is64);
        atomicAdd(&g_cnt[d], 1);
    }
}

__global__ void dinv_kernel() {
    int i = blockIdx.x * blockDim.x + threadIdx.x;
    if (i < N_NODES) {
        float deg = (float)g_cnt[i] + 1.0f;
        g_dinv[i] = rsqrtf(deg);
    }
}

__global__ void scan_kernel() {
    __shared__ int sums[1024];
    const int tid = threadIdx.x;
    const int CHUNK = (N_NODES + 1023) / 1024;
    int begin = tid * CHUNK;
    int end   = min(begin + CHUNK, N_NODES);
    int s = 0;
    for (int i = begin; i < end; i++) s += g_cnt[i];
    sums[tid] = s;
    __syncthreads();
    for (int off = 1; off < 1024; off <<= 1) {
        int v = 0;
        if (tid >= off) v = sums[tid - off];
        __syncthreads();
        if (tid >= off) sums[tid] += v;
        __syncthreads();
    }
    int run = (tid == 0) ? 0 : sums[tid - 1];
    for (int i = begin; i < end; i++) {
        g_rowptr[i] = run;
        g_fill[i]   = run;
        run += g_cnt[i];
    }
    if (tid == 0) g_rowptr[N_NODES] = N_EDGES;
}

__global__ void scatter_kernel(const void* __restrict__ ei) {
    int e = blockIdx.x * blockDim.x + threadIdx.x;
    if (e < N_EDGES) {
        int is64 = g_is64;
        int s = edge_at(ei, e, is64);
        int d = edge_at(ei, (size_t)N_EDGES + e, is64);
        int p = atomicAdd(&g_fill[d], 1);
        g_srcidx[p] = s;
        g_norm[p]   = g_dinv[s] * g_dinv[d];
    }
}

// ---------------- bf16x3 tensor-core GEMM ----------------
// C[M,NN] = A[M,KK] @ B[KK,NN]
// LAYER 0: A = x (fp32, split in-kernel), B = g_w1h/l, C = g_h1
// LAYER 1: A = g_a1h/l (pre-split pairs),  B = g_w2h/l, C = g_h2
template <int BM, int BN, int WARPS_M, int WARPS_N, int NN, int KK, int LAYER>
__global__ void __launch_bounds__(256)
mma_gemm_kernel(const float* __restrict__ A_ext, int M) {
    constexpr int BK   = 32;          // k per tile
    constexpr int KP   = BK / 2;      // uint32 pairs per row (16)
    constexpr int KPP  = KP + 4;      // padded row stride (80B -> conflict-free)
    constexpr int WM = BM / WARPS_M, WN = BN / WARPS_N;
    constexpr int MI = WM / 16, NI = WN / 8;

    __shared__ uint32_t Ah[BM * KPP], Al[BM * KPP];
    __shared__ uint32_t Bh[BN * KPP], Bl[BN * KPP];

    const uint32_t* __restrict__ WhG = (LAYER == 0) ? g_w1h : g_w2h;
    const uint32_t* __restrict__ WlG = (LAYER == 0) ? g_w1l : g_w2l;
    float* __restrict__ C = (LAYER == 0) ? (float*)g_h1 : (float*)g_h2;

    const int tid  = threadIdx.x;
    const int wid  = tid >> 5;
    const int lane = tid & 31;
    const int g    = lane >> 2;
    const int t    = lane & 3;
    const int wm   = (wid / WARPS_N) * WM;
    const int wn   = (wid % WARPS_N) * WN;
    const int block_m = blockIdx.x * BM;

    float acc[MI][NI][4];
#pragma unroll
    for (int mi = 0; mi < MI; mi++)
#pragma unroll
        for (int ni = 0; ni < NI; ni++)
#pragma unroll
            for (int j = 0; j < 4; j++) acc[mi][ni][j] = 0.0f;

    for (int k0 = 0; k0 < KK; k0 += BK) {
        // ---- A tile ----
        if (LAYER == 0) {
#pragma unroll
            for (int i = tid; i < BM * (BK / 4); i += 256) {
                int row = i / (BK / 4);
                int c4  = i % (BK / 4);
                int gm  = block_m + row;
                float4 v = make_float4(0.f, 0.f, 0.f, 0.f);
                if (gm < M) v = *(const float4*)&A_ext[(size_t)gm * KK + k0 + c4 * 4];
                uint32_t h0, l0, h1, l1;
                split2(v.x, v.y, h0, l0);
                split2(v.z, v.w, h1, l1);
                Ah[row * KPP + c4 * 2 + 0] = h0;
                Ah[row * KPP + c4 * 2 + 1] = h1;
                Al[row * KPP + c4 * 2 + 0] = l0;
                Al[row * KPP + c4 * 2 + 1] = l1;
            }
        } else {
#pragma unroll
            for (int i = tid; i < BM * KP; i += 256) {
                int row = i / KP;
                int kp  = i % KP;
                int gm  = block_m + row;
                uint32_t h = 0, l = 0;
                if (gm < M) {
                    h = g_a1h[(size_t)gm * (KK / 2) + k0 / 2 + kp];
                    l = g_a1l[(size_t)gm * (KK / 2) + k0 / 2 + kp];
                }
                Ah[row * KPP + kp] = h;
                Al[row * KPP + kp] = l;
            }
        }
        // ---- B tile: vector copy of pre-split W^T pairs ----
#pragma unroll
        for (int i = tid; i < BN * KP; i += 256) {
            int n  = i / KP;
            int kp = i % KP;
            Bh[n * KPP + kp] = WhG[(size_t)n * (KK / 2) + k0 / 2 + kp];
            Bl[n * KPP + kp] = WlG[(size_t)n * (KK / 2) + k0 / 2 + kp];
        }
        __syncthreads();

        // ---- compute: two k16 steps per tile ----
#pragma unroll
        for (int s = 0; s < 2; s++) {
            const int sp = s * 8;
            uint32_t ah[MI][4], al[MI][4];
#pragma unroll
            for (int mi = 0; mi < MI; mi++) {
                int r = wm + mi * 16;
                ah[mi][0] = Ah[(r + g) * KPP + sp + t];
                ah[mi][1] = Ah[(r + g + 8) * KPP + sp + t];
                ah[mi][2] = Ah[(r + g) * KPP + sp + t + 4];
                ah[mi][3] = Ah[(r + g + 8) * KPP + sp + t + 4];
                al[mi][0] = Al[(r + g) * KPP + sp + t];
                al[mi][1] = Al[(r + g + 8) * KPP + sp + t];
                al[mi][2] = Al[(r + g) * KPP + sp + t + 4];
                al[mi][3] = Al[(r + g + 8) * KPP + sp + t + 4];
            }
            uint32_t bh[NI][2], bl[NI][2];
#pragma unroll
            for (int ni = 0; ni < NI; ni++) {
                int n = wn + ni * 8 + g;
                bh[ni][0] = Bh[n * KPP + sp + t];
                bh[ni][1] = Bh[n * KPP + sp + t + 4];
                bl[ni][0] = Bl[n * KPP + sp + t];
                bl[ni][1] = Bl[n * KPP + sp + t + 4];
            }
#pragma unroll
            for (int mi = 0; mi < MI; mi++)
#pragma unroll
                for (int ni = 0; ni < NI; ni++) {
                    MMA_BF16(acc[mi][ni], ah[mi], bh[ni]);
                    MMA_BF16(acc[mi][ni], ah[mi], bl[ni]);
                    MMA_BF16(acc[mi][ni], al[mi], bh[ni]);
                }
        }
        __syncthreads();
    }

    // ---- epilogue (fp32) ----
#pragma unroll
    for (int mi = 0; mi < MI; mi++) {
#pragma unroll
        for (int ni = 0; ni < NI; ni++) {
            int r0 = block_m + wm + mi * 16 + g;
            int c0 = wn + ni * 8 + 2 * t;
            if (r0 < M)
                *(float2*)&C[(size_t)r0 * NN + c0] =
                    make_float2(acc[mi][ni][0], acc[mi][ni][1]);
            if (r0 + 8 < M)
                *(float2*)&C[(size_t)(r0 + 8) * NN + c0] =
                    make_float2(acc[mi][ni][2], acc[mi][ni][3]);
        }
    }
}

// ---------------- aggregation (one warp per dst node, 4-wide gather pipeline) ----------------
__global__ void agg128_relu_kernel(const float* __restrict__ bias) {
    const float* __restrict__ h = (const float*)g_h1;
    const int warp = blockIdx.x * (blockDim.x >> 5) + (threadIdx.x >> 5);
    const int lane = threadIdx.x & 31;
    if (warp >= N_NODES) return;

    const int start = g_rowptr[warp];
    const int end   = g_rowptr[warp + 1];

    float4 acc = make_float4(0.f, 0.f, 0.f, 0.f);
    for (int base = start; base < end; base += 32) {
        int e = base + lane;
        int s = 0; float nm = 0.f;
        if (e < end) { s = g_srcidx[e]; nm = g_norm[e]; }
        int cnt = min(32, end - base);
        int j = 0;
        for (; j + 4 <= cnt; j += 4) {
            int   s0 = __shfl_sync(0xffffffffu, s, j);
            int   s1 = __shfl_sync(0xffffffffu, s, j + 1);
            int   s2 = __shfl_sync(0xffffffffu, s, j + 2);
            int   s3 = __shfl_sync(0xffffffffu, s, j + 3);
            float n0 = __shfl_sync(0xffffffffu, nm, j);
            float n1 = __shfl_sync(0xffffffffu, nm, j + 1);
            float n2 = __shfl_sync(0xffffffffu, nm, j + 2);
            float n3 = __shfl_sync(0xffffffffu, nm, j + 3);
            float4 v0 = *(const float4*)&h[(size_t)s0 * C_HID + lane * 4];
            float4 v1 = *(const float4*)&h[(size_t)s1 * C_HID + lane * 4];
            float4 v2 = *(const float4*)&h[(size_t)s2 * C_HID + lane * 4];
            float4 v3 = *(const float4*)&h[(size_t)s3 * C_HID + lane * 4];
            acc.x += v0.x * n0 + v1.x * n1 + v2.x * n2 + v3.x * n3;
            acc.y += v0.y * n0 + v1.y * n1 + v2.y * n2 + v3.y * n3;
            acc.z += v0.z * n0 + v1.z * n1 + v2.z * n2 + v3.z * n3;
            acc.w += v0.w * n0 + v1.w * n1 + v2.w * n2 + v3.w * n3;
        }
        for (; j < cnt; j++) {
            int   ss = __shfl_sync(0xffffffffu, s, j);
            float nn = __shfl_sync(0xffffffffu, nm, j);
            float4 v = *(const float4*)&h[(size_t)ss * C_HID + lane * 4];
            acc.x += v.x * nn; acc.y += v.y * nn;
            acc.z += v.z * nn; acc.w += v.w * nn;
        }
    }
    float dv = g_dinv[warp];
    float sn = dv * dv;
    float4 v = *(const float4*)&h[(size_t)warp * C_HID + lane * 4];
    acc.x += v.x * sn; acc.y += v.y * sn; acc.z += v.z * sn; acc.w += v.w * sn;
    const float4 b = *(const float4*)&bias[lane * 4];
    acc.x = fmaxf(acc.x + b.x, 0.f);
    acc.y = fmaxf(acc.y + b.y, 0.f);
    acc.z = fmaxf(acc.z + b.z, 0.f);
    acc.w = fmaxf(acc.w + b.w, 0.f);
    // emit bf16 hi/lo pairs for GEMM2's A operand
    uint32_t h0, l0, h1, l1;
    split2(acc.x, acc.y, h0, l0);
    split2(acc.z, acc.w, h1, l1);
    size_t o = (size_t)warp * (C_HID / 2) + lane * 2;
    g_a1h[o]     = h0;
    g_a1h[o + 1] = h1;
    g_a1l[o]     = l0;
    g_a1l[o + 1] = l1;
}

__global__ void agg64_kernel(const float* __restrict__ bias,
                             float* __restrict__ out) {
    const float* __restrict__ h = (const float*)g_h2;
    const int warp = blockIdx.x * (blockDim.x >> 5) + (threadIdx.x >> 5);
    const int lane = threadIdx.x & 31;
    if (warp >= N_NODES) return;

    const int start = g_rowptr[warp];
    const int end   = g_rowptr[warp + 1];

    float2 acc = make_float2(0.f, 0.f);
    for (int base = start; base < end; base += 32) {
        int e = base + lane;
        int s = 0; float nm = 0.f;
        if (e < end) { s = g_srcidx[e]; nm = g_norm[e]; }
        int cnt = min(32, end - base);
        int j = 0;
        for (; j + 4 <= cnt; j += 4) {
            int   s0 = __shfl_sync(0xffffffffu, s, j);
            int   s1 = __shfl_sync(0xffffffffu, s, j + 1);
            int   s2 = __shfl_sync(0xffffffffu, s, j + 2);
            int   s3 = __shfl_sync(0xffffffffu, s, j + 3);
            float n0 = __shfl_sync(0xffffffffu, nm, j);
            float n1 = __shfl_sync(0xffffffffu, nm, j + 1);
            float n2 = __shfl_sync(0xffffffffu, nm, j + 2);
            float n3 = __shfl_sync(0xffffffffu, nm, j + 3);
            float2 v0 = *(const float2*)&h[(size_t)s0 * C_OUT + lane * 2];
            float2 v1 = *(const float2*)&h[(size_t)s1 * C_OUT + lane * 2];
            float2 v2 = *(const float2*)&h[(size_t)s2 * C_OUT + lane * 2];
            float2 v3 = *(const float2*)&h[(size_t)s3 * C_OUT + lane * 2];
            acc.x += v0.x * n0 + v1.x * n1 + v2.x * n2 + v3.x * n3;
            acc.y += v0.y * n0 + v1.y * n1 + v2.y * n2 + v3.y * n3;
        }
        for (; j < cnt; j++) {
            int   ss = __shfl_sync(0xffffffffu, s, j);
            float nn = __shfl_sync(0xffffffffu, nm, j);
            float2 v = *(const float2*)&h[(size_t)ss * C_OUT + lane * 2];
            acc.x += v.x * nn; acc.y += v.y * nn;
        }
    }
    float dv = g_dinv[warp];
    float sn = dv * dv;
    float2 v = *(const float2*)&h[(size_t)warp * C_OUT + lane * 2];
    acc.x += v.x * sn; acc.y += v.y * sn;
    const float2 b = *(const float2*)&bias[lane * 2];
    acc.x += b.x; acc.y += b.y;
    *(float2*)&out[(size_t)warp * C_OUT + lane * 2] = acc;
}

// ---------------- launch ----------------
extern "C" void kernel_launch(void* const* d_in, const int* in_sizes, int n_in,
                              void* d_out, int out_size) {
    const float* x  = (const float*)d_in[0];
    const void*  ei = d_in[1];
    const float* W1 = (const float*)d_in[2];
    const float* b1 = (const float*)d_in[3];
    const float* W2 = (const float*)d_in[4];
    const float* b2 = (const float*)d_in[5];
    float* out = (float*)d_out;

    const int TB = 256;
    const int nodeBlocks = (N_NODES + TB - 1) / TB;
    const int edgeBlocks = (N_EDGES + TB - 1) / TB;

    detect_dtype_kernel<<<1, 1>>>(ei);
    wprep_kernel<0><<<(C_HID * C_IN / 2 + TB - 1) / TB, TB>>>(W1);
    wprep_kernel<1><<<(C_OUT * C_HID / 2 + TB - 1) / TB, TB>>>(W2);

    // layer 1 GEMM: g_h1 = x @ W1
    {
        constexpr int BM = 64;
        int grid = (N_NODES + BM - 1) / BM;
        mma_gemm_kernel<BM, 128, 2, 4, C_HID, C_IN, 0><<<grid, 256>>>(x, N_NODES);
    }
    zero_cnt_kernel<<<nodeBlocks, TB>>>();
    count_kernel<<<edgeBlocks, TB>>>(ei);
    dinv_kernel<<<nodeBlocks, TB>>>();
    scan_kernel<<<1, 1024>>>();
    scatter_kernel<<<edgeBlocks, TB>>>(ei);

    // a1 = relu(aggregate(h1) + b1)  -> bf16 hi/lo pairs
    {
        const int WPB = 8;
        int grid = (N_NODES + WPB - 1) / WPB;
        agg128_relu_kernel<<<grid, WPB * 32>>>(b1);
    }
    // layer 2 GEMM: g_h2 = a1 @ W2
    {
        constexpr int BM = 64;
        int grid = (N_NODES + BM - 1) / BM;
        mma_gemm_kernel<BM, 64, 2, 4, C_OUT, C_HID, 1><<<grid, 256>>>(nullptr, N_NODES);
    }
    // out = aggregate(h2) + b2
    {
        const int WPB = 8;
        int grid = (N_NODES + WPB - 1) / WPB;
        agg64_kernel<<<grid, WPB * 32>>>(b2, out);
    }
}

// round 10
// speedup vs baseline: 1.6742x; 1.2905x over previous
#include <cuda_runtime.h>
#include <cuda_bf16.h>
#include <stdint.h>

#define N_NODES 50000
#define N_EDGES 800000
#define C_IN    256
#define C_HID   128
#define C_OUT   64

#define SCAN_TB 256
#define SCAN_NB ((N_NODES + SCAN_TB - 1) / SCAN_TB)   // 196

// ---------------- scratch (static device globals; no allocation) ----------------
// RULE (learned R1/R7): never pass these as kernel arguments from host code.
__device__ int   g_is64;
__device__ int   g_cnt[N_NODES];
__device__ float g_dinv[N_NODES];
__device__ int   g_rowptr[N_NODES + 1];
__device__ int   g_fill[N_NODES];
__device__ int   g_srcidx[N_EDGES];
__device__ float g_norm[N_EDGES];
__device__ int   g_bsum[SCAN_NB];
__device__ int   g_boff[SCAN_NB];
__device__ float g_h1[(size_t)N_NODES * C_HID];
__device__ float g_h2[(size_t)N_NODES * C_OUT];
__device__ uint32_t g_a1h[(size_t)N_NODES * (C_HID / 2)];
__device__ uint32_t g_a1l[(size_t)N_NODES * (C_HID / 2)];
__device__ uint32_t g_w1h[C_HID * (C_IN / 2)];
__device__ uint32_t g_w1l[C_HID * (C_IN / 2)];
__device__ uint32_t g_w2h[C_OUT * (C_HID / 2)];
__device__ uint32_t g_w2l[C_OUT * (C_HID / 2)];

// ---------------- helpers ----------------
__device__ __forceinline__ uint32_t packbf2(float x, float y) {
    __nv_bfloat162 v = __floats2bfloat162_rn(x, y);
    return *(uint32_t*)&v;
}
__device__ __forceinline__ void split2(float x, float y, uint32_t& hi, uint32_t& lo) {
    __nv_bfloat16 hx = __float2bfloat16_rn(x);
    __nv_bfloat16 hy = __float2bfloat16_rn(y);
    __nv_bfloat162 h = __halves2bfloat162(hx, hy);
    hi = *(uint32_t*)&h;
    lo = packbf2(x - __bfloat162float(hx), y - __bfloat162float(hy));
}

#define MMA_BF16(c, a, b)                                                     \
    asm volatile(                                                             \
        "mma.sync.aligned.m16n8k16.row.col.f32.bf16.bf16.f32 "                \
        "{%0,%1,%2,%3},{%4,%5,%6,%7},{%8,%9},{%0,%1,%2,%3};"                  \
        : "+f"((c)[0]), "+f"((c)[1]), "+f"((c)[2]), "+f"((c)[3])              \
        : "r"((a)[0]), "r"((a)[1]), "r"((a)[2]), "r"((a)[3]),                 \
          "r"((b)[0]), "r"((b)[1]))

// ---------------- edge dtype detection ----------------
__global__ void detect_dtype_kernel(const void* ei) {
    const long long* e64 = (const long long*)ei;
    bool ok = true;
    for (int i = 0; i < 8; i++) {
        long long s = e64[i];
        long long d = e64[N_EDGES + i];
        if (s < 0 || s >= N_NODES || d < 0 || d >= N_NODES) ok = false;
    }
    g_is64 = ok ? 1 : 0;
}

__device__ __forceinline__ int edge_at(const void* ei, size_t idx, int is64) {
    long long v;
    if (is64) v = ((const long long*)ei)[idx];
    else      v = (long long)((const int*)ei)[idx];
    v = v < 0 ? 0 : (v >= N_NODES ? N_NODES - 1 : v);
    return (int)v;
}

// ---------------- weight prep ----------------
template <int LAYER>
__global__ void wprep_kernel(const float* __restrict__ W) {
    constexpr int K = (LAYER == 0) ? C_IN  : C_HID;
    constexpr int N = (LAYER == 0) ? C_HID : C_OUT;
    uint32_t* __restrict__ Wh = (LAYER == 0) ? g_w1h : g_w2h;
    uint32_t* __restrict__ Wl = (LAYER == 0) ? g_w1l : g_w2l;
    int idx = blockIdx.x * blockDim.x + threadIdx.x;
    if (idx >= N * (K / 2)) return;
    int n  = idx / (K / 2);
    int kp = idx % (K / 2);
    float f0 = W[(size_t)(2 * kp) * N + n];
    float f1 = W[(size_t)(2 * kp + 1) * N + n];
    uint32_t hi, lo;
    split2(f0, f1, hi, lo);
    Wh[idx] = hi;
    Wl[idx] = lo;
}

// ---------------- CSR build ----------------
__global__ void zero_cnt_kernel() {
    int i = blockIdx.x * blockDim.x + threadIdx.x;
    if (i < N_NODES) g_cnt[i] = 0;
}

__global__ void count_kernel(const void* __restrict__ ei) {
    int e = blockIdx.x * blockDim.x + threadIdx.x;
    if (e < N_EDGES) {
        int d = edge_at(ei, (size_t)N_EDGES + e, g_is64);
        atomicAdd(&g_cnt[d], 1);
    }
}

__global__ void dinv_kernel() {
    int i = blockIdx.x * blockDim.x + threadIdx.x;
    if (i < N_NODES) {
        float deg = (float)g_cnt[i] + 1.0f;
        g_dinv[i] = rsqrtf(deg);
    }
}

// 3-phase parallel exclusive scan of g_cnt -> g_rowptr (+g_fill)
__global__ void scan1_kernel() {
    __shared__ int sm[SCAN_TB];
    int i = blockIdx.x * SCAN_TB + threadIdx.x;
    sm[threadIdx.x] = (i < N_NODES) ? g_cnt[i] : 0;
    __syncthreads();
#pragma unroll
    for (int off = SCAN_TB / 2; off > 0; off >>= 1) {
        if (threadIdx.x < off) sm[threadIdx.x] += sm[threadIdx.x + off];
        __syncthreads();
    }
    if (threadIdx.x == 0) g_bsum[blockIdx.x] = sm[0];
}

__global__ void scan2_kernel() {
    __shared__ int sm[SCAN_TB];
    int tid = threadIdx.x;
    sm[tid] = (tid < SCAN_NB) ? g_bsum[tid] : 0;
    __syncthreads();
#pragma unroll
    for (int off = 1; off < SCAN_TB; off <<= 1) {
        int v = 0;
        if (tid >= off) v = sm[tid - off];
        __syncthreads();
        if (tid >= off) sm[tid] += v;
        __syncthreads();
    }
    if (tid < SCAN_NB) g_boff[tid] = (tid == 0) ? 0 : sm[tid - 1];
}

__global__ void scan3_kernel() {
    __shared__ int sm[SCAN_TB];
    int tid = threadIdx.x;
    int i = blockIdx.x * SCAN_TB + tid;
    sm[tid] = (i < N_NODES) ? g_cnt[i] : 0;
    __syncthreads();
#pragma unroll
    for (int off = 1; off < SCAN_TB; off <<= 1) {
        int v = 0;
        if (tid >= off) v = sm[tid - off];
        __syncthreads();
        if (tid >= off) sm[tid] += v;
        __syncthreads();
    }
    if (i < N_NODES) {
        int excl = ((tid == 0) ? 0 : sm[tid - 1]) + g_boff[blockIdx.x];
        g_rowptr[i] = excl;
        g_fill[i]   = excl;
    }
    if (blockIdx.x == 0 && tid == 0) g_rowptr[N_NODES] = N_EDGES;
}

__global__ void scatter_kernel(const void* __restrict__ ei) {
    int e = blockIdx.x * blockDim.x + threadIdx.x;
    if (e < N_EDGES) {
        int is64 = g_is64;
        int s = edge_at(ei, e, is64);
        int d = edge_at(ei, (size_t)N_EDGES + e, is64);
        int p = atomicAdd(&g_fill[d], 1);
        g_srcidx[p] = s;
        g_norm[p]   = g_dinv[s] * g_dinv[d];
    }
}

// ---------------- bf16x3 tensor-core GEMM ----------------
template <int BM, int BN, int WARPS_M, int WARPS_N, int NN, int KK, int LAYER>
__global__ void __launch_bounds__(256)
mma_gemm_kernel(const float* __restrict__ A_ext, int M) {
    constexpr int BK   = 32;
    constexpr int KP   = BK / 2;
    constexpr int KPP  = KP + 4;
    constexpr int WM = BM / WARPS_M, WN = BN / WARPS_N;
    constexpr int MI = WM / 16, NI = WN / 8;

    __shared__ uint32_t Ah[BM * KPP], Al[BM * KPP];
    __shared__ uint32_t Bh[BN * KPP], Bl[BN * KPP];

    const uint32_t* __restrict__ WhG = (LAYER == 0) ? g_w1h : g_w2h;
    const uint32_t* __restrict__ WlG = (LAYER == 0) ? g_w1l : g_w2l;
    float* __restrict__ C = (LAYER == 0) ? (float*)g_h1 : (float*)g_h2;

    const int tid  = threadIdx.x;
    const int wid  = tid >> 5;
    const int lane = tid & 31;
    const int g    = lane >> 2;
    const int t    = lane & 3;
    const int wm   = (wid / WARPS_N) * WM;
    const int wn   = (wid % WARPS_N) * WN;
    const int block_m = blockIdx.x * BM;

    float acc[MI][NI][4];
#pragma unroll
    for (int mi = 0; mi < MI; mi++)
#pragma unroll
        for (int ni = 0; ni < NI; ni++)
#pragma unroll
            for (int j = 0; j < 4; j++) acc[mi][ni][j] = 0.0f;

    for (int k0 = 0; k0 < KK; k0 += BK) {
        if (LAYER == 0) {
#pragma unroll
            for (int i = tid; i < BM * (BK / 4); i += 256) {
                int row = i / (BK / 4);
                int c4  = i % (BK / 4);
                int gm  = block_m + row;
                float4 v = make_float4(0.f, 0.f, 0.f, 0.f);
                if (gm < M) v = *(const float4*)&A_ext[(size_t)gm * KK + k0 + c4 * 4];
                uint32_t h0, l0, h1, l1;
                split2(v.x, v.y, h0, l0);
                split2(v.z, v.w, h1, l1);
                Ah[row * KPP + c4 * 2 + 0] = h0;
                Ah[row * KPP + c4 * 2 + 1] = h1;
                Al[row * KPP + c4 * 2 + 0] = l0;
                Al[row * KPP + c4 * 2 + 1] = l1;
            }
        } else {
#pragma unroll
            for (int i = tid; i < BM * KP; i += 256) {
                int row = i / KP;
                int kp  = i % KP;
                int gm  = block_m + row;
                uint32_t h = 0, l = 0;
                if (gm < M) {
                    h = g_a1h[(size_t)gm * (KK / 2) + k0 / 2 + kp];
                    l = g_a1l[(size_t)gm * (KK / 2) + k0 / 2 + kp];
                }
                Ah[row * KPP + kp] = h;
                Al[row * KPP + kp] = l;
            }
        }
#pragma unroll
        for (int i = tid; i < BN * KP; i += 256) {
            int n  = i / KP;
            int kp = i % KP;
            Bh[n * KPP + kp] = WhG[(size_t)n * (KK / 2) + k0 / 2 + kp];
            Bl[n * KPP + kp] = WlG[(size_t)n * (KK / 2) + k0 / 2 + kp];
        }
        __syncthreads();

#pragma unroll
        for (int s = 0; s < 2; s++) {
            const int sp = s * 8;
            uint32_t ah[MI][4], al[MI][4];
#pragma unroll
            for (int mi = 0; mi < MI; mi++) {
                int r = wm + mi * 16;
                ah[mi][0] = Ah[(r + g) * KPP + sp + t];
                ah[mi][1] = Ah[(r + g + 8) * KPP + sp + t];
                ah[mi][2] = Ah[(r + g) * KPP + sp + t + 4];
                ah[mi][3] = Ah[(r + g + 8) * KPP + sp + t + 4];
                al[mi][0] = Al[(r + g) * KPP + sp + t];
                al[mi][1] = Al[(r + g + 8) * KPP + sp + t];
                al[mi][2] = Al[(r + g) * KPP + sp + t + 4];
                al[mi][3] = Al[(r + g + 8) * KPP + sp + t + 4];
            }
            uint32_t bh[NI][2], bl[NI][2];
#pragma unroll
            for (int ni = 0; ni < NI; ni++) {
                int n = wn + ni * 8 + g;
                bh[ni][0] = Bh[n * KPP + sp + t];
                bh[ni][1] = Bh[n * KPP + sp + t + 4];
                bl[ni][0] = Bl[n * KPP + sp + t];
                bl[ni][1] = Bl[n * KPP + sp + t + 4];
            }
#pragma unroll
            for (int mi = 0; mi < MI; mi++)
#pragma unroll
                for (int ni = 0; ni < NI; ni++) {
                    MMA_BF16(acc[mi][ni], ah[mi], bh[ni]);
                    MMA_BF16(acc[mi][ni], ah[mi], bl[ni]);
                    MMA_BF16(acc[mi][ni], al[mi], bh[ni]);
                }
        }
        __syncthreads();
    }

#pragma unroll
    for (int mi = 0; mi < MI; mi++) {
#pragma unroll
        for (int ni = 0; ni < NI; ni++) {
            int r0 = block_m + wm + mi * 16 + g;
            int c0 = wn + ni * 8 + 2 * t;
            if (r0 < M)
                *(float2*)&C[(size_t)r0 * NN + c0] =
                    make_float2(acc[mi][ni][0], acc[mi][ni][1]);
            if (r0 + 8 < M)
                *(float2*)&C[(size_t)(r0 + 8) * NN + c0] =
                    make_float2(acc[mi][ni][2], acc[mi][ni][3]);
        }
    }
}

// ---------------- aggregation (one warp per dst node, 8-wide gather pipeline) ----------------
__global__ void agg128_relu_kernel(const float* __restrict__ bias) {
    const float* __restrict__ h = (const float*)g_h1;
    const int warp = blockIdx.x * (blockDim.x >> 5) + (threadIdx.x >> 5);
    const int lane = threadIdx.x & 31;
    if (warp >= N_NODES) return;

    const int start = g_rowptr[warp];
    const int end   = g_rowptr[warp + 1];

    float4 acc = make_float4(0.f, 0.f, 0.f, 0.f);
    for (int base = start; base < end; base += 32) {
        int e = base + lane;
        int s = 0; float nm = 0.f;
        if (e < end) { s = g_srcidx[e]; nm = g_norm[e]; }
        int cnt = min(32, end - base);
        int j = 0;
        for (; j + 8 <= cnt; j += 8) {
            int sv[8]; float nv[8]; float4 vv[8];
#pragma unroll
            for (int u = 0; u < 8; u++) {
                sv[u] = __shfl_sync(0xffffffffu, s, j + u);
                nv[u] = __shfl_sync(0xffffffffu, nm, j + u);
            }
#pragma unroll
            for (int u = 0; u < 8; u++)
                vv[u] = *(const float4*)&h[(size_t)sv[u] * C_HID + lane * 4];
#pragma unroll
            for (int u = 0; u < 8; u++) {
                acc.x += vv[u].x * nv[u];
                acc.y += vv[u].y * nv[u];
                acc.z += vv[u].z * nv[u];
                acc.w += vv[u].w * nv[u];
            }
        }
        for (; j < cnt; j++) {
            int   ss = __shfl_sync(0xffffffffu, s, j);
            float nn = __shfl_sync(0xffffffffu, nm, j);
            float4 v = *(const float4*)&h[(size_t)ss * C_HID + lane * 4];
            acc.x += v.x * nn; acc.y += v.y * nn;
            acc.z += v.z * nn; acc.w += v.w * nn;
        }
    }
    float dv = g_dinv[warp];
    float sn = dv * dv;
    float4 v = *(const float4*)&h[(size_t)warp * C_HID + lane * 4];
    acc.x += v.x * sn; acc.y += v.y * sn; acc.z += v.z * sn; acc.w += v.w * sn;
    const float4 b = *(const float4*)&bias[lane * 4];
    acc.x = fmaxf(acc.x + b.x, 0.f);
    acc.y = fmaxf(acc.y + b.y, 0.f);
    acc.z = fmaxf(acc.z + b.z, 0.f);
    acc.w = fmaxf(acc.w + b.w, 0.f);
    uint32_t h0, l0, h1, l1;
    split2(acc.x, acc.y, h0, l0);
    split2(acc.z, acc.w, h1, l1);
    size_t o = (size_t)warp * (C_HID / 2) + lane * 2;
    g_a1h[o]     = h0;
    g_a1h[o + 1] = h1;
    g_a1l[o]     = l0;
    g_a1l[o + 1] = l1;
}

__global__ void agg64_kernel(const float* __restrict__ bias,
                             float* __restrict__ out) {
    const float* __restrict__ h = (const float*)g_h2;
    const int warp = blockIdx.x * (blockDim.x >> 5) + (threadIdx.x >> 5);
    const int lane = threadIdx.x & 31;
    if (warp >= N_NODES) return;

    const int start = g_rowptr[warp];
    const int end   = g_rowptr[warp + 1];

    float2 acc = make_float2(0.f, 0.f);
    for (int base = start; base < end; base += 32) {
        int e = base + lane;
        int s = 0; float nm = 0.f;
        if (e < end) { s = g_srcidx[e]; nm = g_norm[e]; }
        int cnt = min(32, end - base);
        int j = 0;
        for (; j + 8 <= cnt; j += 8) {
            int sv[8]; float nv[8]; float2 vv[8];
#pragma unroll
            for (int u = 0; u < 8; u++) {
                sv[u] = __shfl_sync(0xffffffffu, s, j + u);
                nv[u] = __shfl_sync(0xffffffffu, nm, j + u);
            }
#pragma unroll
            for (int u = 0; u < 8; u++)
                vv[u] = *(const float2*)&h[(size_t)sv[u] * C_OUT + lane * 2];
#pragma unroll
            for (int u = 0; u < 8; u++) {
                acc.x += vv[u].x * nv[u];
                acc.y += vv[u].y * nv[u];
            }
        }
        for (; j < cnt; j++) {
            int   ss = __shfl_sync(0xffffffffu, s, j);
            float nn = __shfl_sync(0xffffffffu, nm, j);
            float2 v = *(const float2*)&h[(size_t)ss * C_OUT + lane * 2];
            acc.x += v.x * nn; acc.y += v.y * nn;
        }
    }
    float dv = g_dinv[warp];
    float sn = dv * dv;
    float2 v = *(const float2*)&h[(size_t)warp * C_OUT + lane * 2];
    acc.x += v.x * sn; acc.y += v.y * sn;
    const float2 b = *(const float2*)&bias[lane * 2];
    acc.x += b.x; acc.y += b.y;
    *(float2*)&out[(size_t)warp * C_OUT + lane * 2] = acc;
}

// ---------------- launch ----------------
extern "C" void kernel_launch(void* const* d_in, const int* in_sizes, int n_in,
                              void* d_out, int out_size) {
    const float* x  = (const float*)d_in[0];
    const void*  ei = d_in[1];
    const float* W1 = (const float*)d_in[2];
    const float* b1 = (const float*)d_in[3];
    const float* W2 = (const float*)d_in[4];
    const float* b2 = (const float*)d_in[5];
    float* out = (float*)d_out;

    const int TB = 256;
    const int nodeBlocks = (N_NODES + TB - 1) / TB;
    const int edgeBlocks = (N_EDGES + TB - 1) / TB;

    detect_dtype_kernel<<<1, 1>>>(ei);
    wprep_kernel<0><<<(C_HID * C_IN / 2 + TB - 1) / TB, TB>>>(W1);
    wprep_kernel<1><<<(C_OUT * C_HID / 2 + TB - 1) / TB, TB>>>(W2);

    // layer 1 GEMM: g_h1 = x @ W1  (128x128 tile)
    {
        constexpr int BM = 128;
        int grid = (N_NODES + BM - 1) / BM;
        mma_gemm_kernel<BM, 128, 2, 4, C_HID, C_IN, 0><<<grid, 256>>>(x, N_NODES);
    }
    zero_cnt_kernel<<<nodeBlocks, TB>>>();
    count_kernel<<<edgeBlocks, TB>>>(ei);
    dinv_kernel<<<nodeBlocks, TB>>>();
    scan1_kernel<<<SCAN_NB, SCAN_TB>>>();
    scan2_kernel<<<1, SCAN_TB>>>();
    scan3_kernel<<<SCAN_NB, SCAN_TB>>>();
    scatter_kernel<<<edgeBlocks, TB>>>(ei);

    // a1 = relu(aggregate(h1) + b1)  -> bf16 hi/lo pairs
    {
        const int WPB = 8;
        int grid = (N_NODES + WPB - 1) / WPB;
        agg128_relu_kernel<<<grid, WPB * 32>>>(b1);
    }
    // layer 2 GEMM: g_h2 = a1 @ W2
    {
        constexpr int BM = 64;
        int grid = (N_NODES + BM - 1) / BM;
        mma_gemm_kernel<BM, 64, 2, 4, C_OUT, C_HID, 1><<<grid, 256>>>(nullptr, N_NODES);
    }
    // out = aggregate(h2) + b2
    {
        const int WPB = 8;
        int grid = (N_NODES + WPB - 1) / WPB;
        agg64_kernel<<<grid, WPB * 32>>>(b2, out);
    }
}

// round 11
// speedup vs baseline: 1.8259x; 1.0906x over previous
#include <cuda_runtime.h>
#include <cuda_bf16.h>
#include <stdint.h>

#define N_NODES 50000
#define N_EDGES 800000
#define C_IN    256
#define C_HID   128
#define C_OUT   64

#define SCAN_TB 256
#define SCAN_NB ((N_NODES + SCAN_TB - 1) / SCAN_TB)   // 196

// ---------------- scratch (static device globals; no allocation) ----------------
// RULE (learned R1/R7): never pass these as kernel arguments from host code.
__device__ int   g_is64;
__device__ int   g_cnt[N_NODES];
__device__ float g_dinv[N_NODES];
__device__ int   g_rowptr[N_NODES + 1];
__device__ int   g_fill[N_NODES];
__device__ int   g_srcidx[N_EDGES];
__device__ float g_norm[N_EDGES];
__device__ int   g_bsum[SCAN_NB];
__device__ int   g_boff[SCAN_NB];
__device__ float g_h1[(size_t)N_NODES * C_HID];
__device__ float g_h2[(size_t)N_NODES * C_OUT];
__device__ uint32_t g_a1h[(size_t)N_NODES * (C_HID / 2)];
__device__ uint32_t g_a1l[(size_t)N_NODES * (C_HID / 2)];
__device__ uint32_t g_w1h[C_HID * (C_IN / 2)];
__device__ uint32_t g_w1l[C_HID * (C_IN / 2)];
__device__ uint32_t g_w2h[C_OUT * (C_HID / 2)];
__device__ uint32_t g_w2l[C_OUT * (C_HID / 2)];

// ---------------- helpers ----------------
__device__ __forceinline__ uint32_t packbf2(float x, float y) {
    __nv_bfloat162 v = __floats2bfloat162_rn(x, y);
    return *(uint32_t*)&v;
}
__device__ __forceinline__ void split2(float x, float y, uint32_t& hi, uint32_t& lo) {
    __nv_bfloat16 hx = __float2bfloat16_rn(x);
    __nv_bfloat16 hy = __float2bfloat16_rn(y);
    __nv_bfloat162 h = __halves2bfloat162(hx, hy);
    hi = *(uint32_t*)&h;
    lo = packbf2(x - __bfloat162float(hx), y - __bfloat162float(hy));
}

#define MMA_BF16(c, a, b)                                                     \
    asm volatile(                                                             \
        "mma.sync.aligned.m16n8k16.row.col.f32.bf16.bf16.f32 "                \
        "{%0,%1,%2,%3},{%4,%5,%6,%7},{%8,%9},{%0,%1,%2,%3};"                  \
        : "+f"((c)[0]), "+f"((c)[1]), "+f"((c)[2]), "+f"((c)[3])              \
        : "r"((a)[0]), "r"((a)[1]), "r"((a)[2]), "r"((a)[3]),                 \
          "r"((b)[0]), "r"((b)[1]))

// ---------------- edge dtype detection ----------------
__global__ void detect_dtype_kernel(const void* ei) {
    const long long* e64 = (const long long*)ei;
    bool ok = true;
    for (int i = 0; i < 8; i++) {
        long long s = e64[i];
        long long d = e64[N_EDGES + i];
        if (s < 0 || s >= N_NODES || d < 0 || d >= N_NODES) ok = false;
    }
    g_is64 = ok ? 1 : 0;
}

__device__ __forceinline__ int edge_at(const void* ei, size_t idx, int is64) {
    long long v;
    if (is64) v = ((const long long*)ei)[idx];
    else      v = (long long)((const int*)ei)[idx];
    v = v < 0 ? 0 : (v >= N_NODES ? N_NODES - 1 : v);
    return (int)v;
}

// ---------------- weight prep ----------------
template <int LAYER>
__global__ void wprep_kernel(const float* __restrict__ W) {
    constexpr int K = (LAYER == 0) ? C_IN  : C_HID;
    constexpr int N = (LAYER == 0) ? C_HID : C_OUT;
    uint32_t* __restrict__ Wh = (LAYER == 0) ? g_w1h : g_w2h;
    uint32_t* __restrict__ Wl = (LAYER == 0) ? g_w1l : g_w2l;
    int idx = blockIdx.x * blockDim.x + threadIdx.x;
    if (idx >= N * (K / 2)) return;
    int n  = idx / (K / 2);
    int kp = idx % (K / 2);
    float f0 = W[(size_t)(2 * kp) * N + n];
    float f1 = W[(size_t)(2 * kp + 1) * N + n];
    uint32_t hi, lo;
    split2(f0, f1, hi, lo);
    Wh[idx] = hi;
    Wl[idx] = lo;
}

// ---------------- CSR build ----------------
__global__ void zero_cnt_kernel() {
    int i = blockIdx.x * blockDim.x + threadIdx.x;
    if (i < N_NODES) g_cnt[i] = 0;
}

__global__ void count_kernel(const void* __restrict__ ei) {
    int e = blockIdx.x * blockDim.x + threadIdx.x;
    if (e < N_EDGES) {
        int d = edge_at(ei, (size_t)N_EDGES + e, g_is64);
        atomicAdd(&g_cnt[d], 1);
    }
}

__global__ void dinv_kernel() {
    int i = blockIdx.x * blockDim.x + threadIdx.x;
    if (i < N_NODES) {
        float deg = (float)g_cnt[i] + 1.0f;
        g_dinv[i] = rsqrtf(deg);
    }
}

// 3-phase parallel exclusive scan
__global__ void scan1_kernel() {
    __shared__ int sm[SCAN_TB];
    int i = blockIdx.x * SCAN_TB + threadIdx.x;
    sm[threadIdx.x] = (i < N_NODES) ? g_cnt[i] : 0;
    __syncthreads();
#pragma unroll
    for (int off = SCAN_TB / 2; off > 0; off >>= 1) {
        if (threadIdx.x < off) sm[threadIdx.x] += sm[threadIdx.x + off];
        __syncthreads();
    }
    if (threadIdx.x == 0) g_bsum[blockIdx.x] = sm[0];
}

__global__ void scan2_kernel() {
    __shared__ int sm[SCAN_TB];
    int tid = threadIdx.x;
    sm[tid] = (tid < SCAN_NB) ? g_bsum[tid] : 0;
    __syncthreads();
#pragma unroll
    for (int off = 1; off < SCAN_TB; off <<= 1) {
        int v = 0;
        if (tid >= off) v = sm[tid - off];
        __syncthreads();
        if (tid >= off) sm[tid] += v;
        __syncthreads();
    }
    if (tid < SCAN_NB) g_boff[tid] = (tid == 0) ? 0 : sm[tid - 1];
}

__global__ void scan3_kernel() {
    __shared__ int sm[SCAN_TB];
    int tid = threadIdx.x;
    int i = blockIdx.x * SCAN_TB + tid;
    sm[tid] = (i < N_NODES) ? g_cnt[i] : 0;
    __syncthreads();
#pragma unroll
    for (int off = 1; off < SCAN_TB; off <<= 1) {
        int v = 0;
        if (tid >= off) v = sm[tid - off];
        __syncthreads();
        if (tid >= off) sm[tid] += v;
        __syncthreads();
    }
    if (i < N_NODES) {
        int excl = ((tid == 0) ? 0 : sm[tid - 1]) + g_boff[blockIdx.x];
        g_rowptr[i] = excl;
        g_fill[i]   = excl;
    }
    if (blockIdx.x == 0 && tid == 0) g_rowptr[N_NODES] = N_EDGES;
}

__global__ void scatter_kernel(const void* __restrict__ ei) {
    int e = blockIdx.x * blockDim.x + threadIdx.x;
    if (e < N_EDGES) {
        int is64 = g_is64;
        int s = edge_at(ei, e, is64);
        int d = edge_at(ei, (size_t)N_EDGES + e, is64);
        int p = atomicAdd(&g_fill[d], 1);
        g_srcidx[p] = s;
        g_norm[p]   = g_dinv[s] * g_dinv[d];
    }
}

// ---------------- bf16x3 tensor-core GEMM, double-buffered pipeline ----------------
// C[M,NN] = A[M,KK] @ B[KK,NN]
// LAYER 0: A = x (fp32, split in-kernel), C = g_h1.  LAYER 1: A = g_a1h/l, C = g_h2.
template <int BM, int BN, int WARPS_M, int WARPS_N, int NN, int KK, int LAYER>
__global__ void __launch_bounds__(256)
mma_gemm_kernel(const float* __restrict__ A_ext, int M) {
    constexpr int BK  = 32;
    constexpr int KP  = BK / 2;       // 16 uint32 pairs
    constexpr int KPP = KP + 4;       // padded stride, conflict-free
    constexpr int WM = BM / WARPS_M, WN = BN / WARPS_N;
    constexpr int MI = WM / 16, NI = WN / 8;
    constexpr int ALD0 = BM * (BK / 4) / 256;   // float4 loads per thread (layer 0)
    constexpr int ALD1 = BM * KP / 256;         // pair loads per thread (layer 1)
    constexpr int BLD  = BN * KP / 256;         // pair loads per thread (B)
    constexpr int ASZ = BM * KPP;
    constexpr int BSZ = BN * KPP;

    extern __shared__ uint32_t smp[];
    uint32_t* Ah = smp;                   // [2][ASZ]
    uint32_t* Al = Ah + 2 * ASZ;
    uint32_t* Bh = Al + 2 * ASZ;          // [2][BSZ]
    uint32_t* Bl = Bh + 2 * BSZ;

    const uint32_t* __restrict__ WhG = (LAYER == 0) ? g_w1h : g_w2h;
    const uint32_t* __restrict__ WlG = (LAYER == 0) ? g_w1l : g_w2l;
    float* __restrict__ C = (LAYER == 0) ? (float*)g_h1 : (float*)g_h2;

    const int tid  = threadIdx.x;
    const int wid  = tid >> 5;
    const int lane = tid & 31;
    const int g    = lane >> 2;
    const int t    = lane & 3;
    const int wm   = (wid / WARPS_N) * WM;
    const int wn   = (wid % WARPS_N) * WN;
    const int block_m = blockIdx.x * BM;

    // per-thread staging registers
    float4   ra0[ALD0 > 0 ? ALD0 : 1];
    uint32_t ra1h[ALD1], ra1l[ALD1];
    uint32_t rbh[BLD], rbl[BLD];

    float acc[MI][NI][4];
#pragma unroll
    for (int mi = 0; mi < MI; mi++)
#pragma unroll
        for (int ni = 0; ni < NI; ni++)
#pragma unroll
            for (int j = 0; j < 4; j++) acc[mi][ni][j] = 0.0f;

    // ---- load tile (global -> regs) ----
    auto load_tile = [&](int k0) {
        if (LAYER == 0) {
#pragma unroll
            for (int u = 0; u < ALD0; u++) {
                int i = u * 256 + tid;
                int row = i / (BK / 4);
                int c4  = i % (BK / 4);
                int gm  = block_m + row;
                ra0[u] = (gm < M) ? *(const float4*)&A_ext[(size_t)gm * KK + k0 + c4 * 4]
                                  : make_float4(0.f, 0.f, 0.f, 0.f);
            }
        } else {
#pragma unroll
            for (int u = 0; u < ALD1; u++) {
                int i = u * 256 + tid;
                int row = i / KP;
                int kp  = i % KP;
                int gm  = block_m + row;
                ra1h[u] = (gm < M) ? g_a1h[(size_t)gm * (KK / 2) + k0 / 2 + kp] : 0;
                ra1l[u] = (gm < M) ? g_a1l[(size_t)gm * (KK / 2) + k0 / 2 + kp] : 0;
            }
        }
#pragma unroll
        for (int u = 0; u < BLD; u++) {
            int i = u * 256 + tid;
            int n  = i / KP;
            int kp = i % KP;
            rbh[u] = WhG[(size_t)n * (KK / 2) + k0 / 2 + kp];
            rbl[u] = WlG[(size_t)n * (KK / 2) + k0 / 2 + kp];
        }
    };

    // ---- store tile (regs -> smem stage) ----
    auto store_tile = [&](int st) {
        uint32_t* ah = Ah + st * ASZ;
        uint32_t* al = Al + st * ASZ;
        uint32_t* bh = Bh + st * BSZ;
        uint32_t* bl = Bl + st * BSZ;
        if (LAYER == 0) {
#pragma unroll
            for (int u = 0; u < ALD0; u++) {
                int i = u * 256 + tid;
                int row = i / (BK / 4);
                int c4  = i % (BK / 4);
                uint32_t h0, l0, h1, l1;
                split2(ra0[u].x, ra0[u].y, h0, l0);
                split2(ra0[u].z, ra0[u].w, h1, l1);
                ah[row * KPP + c4 * 2 + 0] = h0;
                ah[row * KPP + c4 * 2 + 1] = h1;
                al[row * KPP + c4 * 2 + 0] = l0;
                al[row * KPP + c4 * 2 + 1] = l1;
            }
        } else {
#pragma unroll
            for (int u = 0; u < ALD1; u++) {
                int i = u * 256 + tid;
                int row = i / KP;
                int kp  = i % KP;
                ah[row * KPP + kp] = ra1h[u];
                al[row * KPP + kp] = ra1l[u];
            }
        }
#pragma unroll
        for (int u = 0; u < BLD; u++) {
            int i = u * 256 + tid;
            int n  = i / KP;
            int kp = i % KP;
            bh[n * KPP + kp] = rbh[u];
            bl[n * KPP + kp] = rbl[u];
        }
    };

    // ---- compute one stage ----
    auto compute = [&](int st) {
        const uint32_t* ahp = Ah + st * ASZ;
        const uint32_t* alp = Al + st * ASZ;
        const uint32_t* bhp = Bh + st * BSZ;
        const uint32_t* blp = Bl + st * BSZ;
#pragma unroll
        for (int s = 0; s < 2; s++) {
            const int sp = s * 8;
            uint32_t ah[MI][4], al[MI][4];
#pragma unroll
            for (int mi = 0; mi < MI; mi++) {
                int r = wm + mi * 16;
                ah[mi][0] = ahp[(r + g) * KPP + sp + t];
                ah[mi][1] = ahp[(r + g + 8) * KPP + sp + t];
                ah[mi][2] = ahp[(r + g) * KPP + sp + t + 4];
                ah[mi][3] = ahp[(r + g + 8) * KPP + sp + t + 4];
                al[mi][0] = alp[(r + g) * KPP + sp + t];
                al[mi][1] = alp[(r + g + 8) * KPP + sp + t];
                al[mi][2] = alp[(r + g) * KPP + sp + t + 4];
                al[mi][3] = alp[(r + g + 8) * KPP + sp + t + 4];
            }
            uint32_t bh[NI][2], bl[NI][2];
#pragma unroll
            for (int ni = 0; ni < NI; ni++) {
                int n = wn + ni * 8 + g;
                bh[ni][0] = bhp[n * KPP + sp + t];
                bh[ni][1] = bhp[n * KPP + sp + t + 4];
                bl[ni][0] = blp[n * KPP + sp + t];
                bl[ni][1] = blp[n * KPP + sp + t + 4];
            }
#pragma unroll
            for (int mi = 0; mi < MI; mi++)
#pragma unroll
                for (int ni = 0; ni < NI; ni++) {
                    MMA_BF16(acc[mi][ni], ah[mi], bh[ni]);
                    MMA_BF16(acc[mi][ni], ah[mi], bl[ni]);
                    MMA_BF16(acc[mi][ni], al[mi], bh[ni]);
                }
        }
    };

    // ---- pipelined mainloop ----
    int st = 0;
    load_tile(0);
    store_tile(st);
    __syncthreads();
    for (int k0 = 0; k0 < KK; k0 += BK) {
        const bool has_next = (k0 + BK < KK);
        if (has_next) load_tile(k0 + BK);   // LDGs in flight during compute
        compute(st);
        if (has_next) {
            store_tile(st ^ 1);
            __syncthreads();
            st ^= 1;
        }
    }

    // ---- epilogue ----
#pragma unroll
    for (int mi = 0; mi < MI; mi++) {
#pragma unroll
        for (int ni = 0; ni < NI; ni++) {
            int r0 = block_m + wm + mi * 16 + g;
            int c0 = wn + ni * 8 + 2 * t;
            if (r0 < M)
                *(float2*)&C[(size_t)r0 * NN + c0] =
                    make_float2(acc[mi][ni][0], acc[mi][ni][1]);
            if (r0 + 8 < M)
                *(float2*)&C[(size_t)(r0 + 8) * NN + c0] =
                    make_float2(acc[mi][ni][2], acc[mi][ni][3]);
        }
    }
}

// ---------------- aggregation (one warp per dst node, 8-wide gather pipeline) ----------------
__global__ void agg128_relu_kernel(const float* __restrict__ bias) {
    const float* __restrict__ h = (const float*)g_h1;
    const int warp = blockIdx.x * (blockDim.x >> 5) + (threadIdx.x >> 5);
    const int lane = threadIdx.x & 31;
    if (warp >= N_NODES) return;

    const int start = g_rowptr[warp];
    const int end   = g_rowptr[warp + 1];

    float4 acc = make_float4(0.f, 0.f, 0.f, 0.f);
    for (int base = start; base < end; base += 32) {
        int e = base + lane;
        int s = 0; float nm = 0.f;
        if (e < end) { s = g_srcidx[e]; nm = g_norm[e]; }
        int cnt = min(32, end - base);
        int j = 0;
        for (; j + 8 <= cnt; j += 8) {
            int sv[8]; float nv[8]; float4 vv[8];
#pragma unroll
            for (int u = 0; u < 8; u++) {
                sv[u] = __shfl_sync(0xffffffffu, s, j + u);
                nv[u] = __shfl_sync(0xffffffffu, nm, j + u);
            }
#pragma unroll
            for (int u = 0; u < 8; u++)
                vv[u] = *(const float4*)&h[(size_t)sv[u] * C_HID + lane * 4];
#pragma unroll
            for (int u = 0; u < 8; u++) {
                acc.x += vv[u].x * nv[u];
                acc.y += vv[u].y * nv[u];
                acc.z += vv[u].z * nv[u];
                acc.w += vv[u].w * nv[u];
            }
        }
        for (; j < cnt; j++) {
            int   ss = __shfl_sync(0xffffffffu, s, j);
            float nn = __shfl_sync(0xffffffffu, nm, j);
            float4 v = *(const float4*)&h[(size_t)ss * C_HID + lane * 4];
            acc.x += v.x * nn; acc.y += v.y * nn;
            acc.z += v.z * nn; acc.w += v.w * nn;
        }
    }
    float dv = g_dinv[warp];
    float sn = dv * dv;
    float4 v = *(const float4*)&h[(size_t)warp * C_HID + lane * 4];
    acc.x += v.x * sn; acc.y += v.y * sn; acc.z += v.z * sn; acc.w += v.w * sn;
    const float4 b = *(const float4*)&bias[lane * 4];
    acc.x = fmaxf(acc.x + b.x, 0.f);
    acc.y = fmaxf(acc.y + b.y, 0.f);
    acc.z = fmaxf(acc.z + b.z, 0.f);
    acc.w = fmaxf(acc.w + b.w, 0.f);
    uint32_t h0, l0, h1, l1;
    split2(acc.x, acc.y, h0, l0);
    split2(acc.z, acc.w, h1, l1);
    size_t o = (size_t)warp * (C_HID / 2) + lane * 2;
    g_a1h[o]     = h0;
    g_a1h[o + 1] = h1;
    g_a1l[o]     = l0;
    g_a1l[o + 1] = l1;
}

__global__ void agg64_kernel(const float* __restrict__ bias,
                             float* __restrict__ out) {
    const float* __restrict__ h = (const float*)g_h2;
    const int warp = blockIdx.x * (blockDim.x >> 5) + (threadIdx.x >> 5);
    const int lane = threadIdx.x & 31;
    if (warp >= N_NODES) return;

    const int start = g_rowptr[warp];
    const int end   = g_rowptr[warp + 1];

    float2 acc = make_float2(0.f, 0.f);
    for (int base = start; base < end; base += 32) {
        int e = base + lane;
        int s = 0; float nm = 0.f;
        if (e < end) { s = g_srcidx[e]; nm = g_norm[e]; }
        int cnt = min(32, end - base);
        int j = 0;
        for (; j + 8 <= cnt; j += 8) {
            int sv[8]; float nv[8]; float2 vv[8];
#pragma unroll
            for (int u = 0; u < 8; u++) {
                sv[u] = __shfl_sync(0xffffffffu, s, j + u);
                nv[u] = __shfl_sync(0xffffffffu, nm, j + u);
            }
#pragma unroll
            for (int u = 0; u < 8; u++)
                vv[u] = *(const float2*)&h[(size_t)sv[u] * C_OUT + lane * 2];
#pragma unroll
            for (int u = 0; u < 8; u++) {
                acc.x += vv[u].x * nv[u];
                acc.y += vv[u].y * nv[u];
            }
        }
        for (; j < cnt; j++) {
            int   ss = __shfl_sync(0xffffffffu, s, j);
            float nn = __shfl_sync(0xffffffffu, nm, j);
            float2 v = *(const float2*)&h[(size_t)ss * C_OUT + lane * 2];
            acc.x += v.x * nn; acc.y += v.y * nn;
        }
    }
    float dv = g_dinv[warp];
    float sn = dv * dv;
    float2 v = *(const float2*)&h[(size_t)warp * C_OUT + lane * 2];
    acc.x += v.x * sn; acc.y += v.y * sn;
    const float2 b = *(const float2*)&bias[lane * 2];
    acc.x += b.x; acc.y += b.y;
    *(float2*)&out[(size_t)warp * C_OUT + lane * 2] = acc;
}

// ---------------- launch ----------------
extern "C" void kernel_launch(void* const* d_in, const int* in_sizes, int n_in,
                              void* d_out, int out_size) {
    const float* x  = (const float*)d_in[0];
    const void*  ei = d_in[1];
    const float* W1 = (const float*)d_in[2];
    const float* b1 = (const float*)d_in[3];
    const float* W2 = (const float*)d_in[4];
    const float* b2 = (const float*)d_in[5];
    float* out = (float*)d_out;

    const int TB = 256;
    const int nodeBlocks = (N_NODES + TB - 1) / TB;
    const int edgeBlocks = (N_EDGES + TB - 1) / TB;

    detect_dtype_kernel<<<1, 1>>>(ei);
    wprep_kernel<0><<<(C_HID * C_IN / 2 + TB - 1) / TB, TB>>>(W1);
    wprep_kernel<1><<<(C_OUT * C_HID / 2 + TB - 1) / TB, TB>>>(W2);

    // layer 1 GEMM: g_h1 = x @ W1 (BM=64, double-buffered; 61440 B dyn smem)
    {
        constexpr int BM = 64;
        constexpr int SMEM = 4 * 20 * (BM + 128) * 4;   // 4*KPP*(BM+BN) u32 -> bytes
        auto kfn = mma_gemm_kernel<BM, 128, 2, 4, C_HID, C_IN, 0>;
        cudaFuncSetAttribute(kfn, cudaFuncAttributeMaxDynamicSharedMemorySize, SMEM);
        int grid = (N_NODES + BM - 1) / BM;
        kfn<<<grid, 256, SMEM>>>(x, N_NODES);
    }
    zero_cnt_kernel<<<nodeBlocks, TB>>>();
    count_kernel<<<edgeBlocks, TB>>>(ei);
    dinv_kernel<<<nodeBlocks, TB>>>();
    scan1_kernel<<<SCAN_NB, SCAN_TB>>>();
    scan2_kernel<<<1, SCAN_TB>>>();
    scan3_kernel<<<SCAN_NB, SCAN_TB>>>();
    scatter_kernel<<<edgeBlocks, TB>>>(ei);

    // a1 = relu(aggregate(h1) + b1)  -> bf16 hi/lo pairs
    {
        const int WPB = 8;
        int grid = (N_NODES + WPB - 1) / WPB;
        agg128_relu_kernel<<<grid, WPB * 32>>>(b1);
    }
    // layer 2 GEMM: g_h2 = a1 @ W2 (40960 B dyn smem)
    {
        constexpr int BM = 64;
        constexpr int SMEM = 4 * 20 * (BM + 64) * 4;
        auto kfn = mma_gemm_kernel<BM, 64, 2, 4, C_OUT, C_HID, 1>;
        cudaFuncSetAttribute(kfn, cudaFuncAttributeMaxDynamicSharedMemorySize, SMEM);
        int grid = (N_NODES + BM - 1) / BM;
        kfn<<<grid, 256, SMEM>>>(nullptr, N_NODES);
    }
    // out = aggregate(h2) + b2
    {
        const int WPB = 8;
        int grid = (N_NODES + WPB - 1) / WPB;
        agg64_kernel<<<grid, WPB * 32>>>(b2, out);
    }
}